// round 1
// baseline (speedup 1.0000x reference)
#include <cuda_runtime.h>
#include <math.h>

// Problem constants
#define BWIN   2048      // number of windows (batch)
#define SEQ    64        // tokens per window
#define DIM    256
#define HEADS  8
#define HD     32        // head dim
#define NW     64        // mask windows
#define KDIM   256       // GEMM K
#define TBL    225       // (2*8-1)*(2*8-1)
#define CPBH   512

// Scratch (device globals: allowed; no allocations)
__device__ float g_Q[BWIN * HEADS * SEQ * HD];
__device__ float g_K[BWIN * HEADS * SEQ * HD];
__device__ float g_V[BWIN * HEADS * SEQ * HD];
__device__ float g_O[BWIN * SEQ * DIM];
__device__ float g_table[TBL * HEADS];
__device__ float g_bias[HEADS * SEQ * SEQ];

// ---------------------------------------------------------------------------
// Kernel 1: CPB MLP  table[p][h] = sum_j relu(c0*w1[j][0]+c1*w1[j][1]+b1[j]) * w2[h][j]
// grid = TBL blocks, 128 threads
// ---------------------------------------------------------------------------
__global__ __launch_bounds__(128) void cpb_table_kernel(
    const float* __restrict__ w1, const float* __restrict__ b1,
    const float* __restrict__ w2, const float* __restrict__ coords)
{
    int p = blockIdx.x;
    float c0 = coords[2 * p + 0];
    float c1 = coords[2 * p + 1];
    float acc[HEADS];
#pragma unroll
    for (int h = 0; h < HEADS; ++h) acc[h] = 0.f;

    for (int j = threadIdx.x; j < CPBH; j += 128) {
        float hid = fmaf(w1[2 * j], c0, fmaf(w1[2 * j + 1], c1, b1[j]));
        hid = fmaxf(hid, 0.f);
#pragma unroll
        for (int h = 0; h < HEADS; ++h)
            acc[h] = fmaf(hid, w2[h * CPBH + j], acc[h]);
    }
    // reduce across warps
    int lane = threadIdx.x & 31, warp = threadIdx.x >> 5;
#pragma unroll
    for (int h = 0; h < HEADS; ++h)
#pragma unroll
        for (int off = 16; off; off >>= 1)
            acc[h] += __shfl_xor_sync(0xffffffffu, acc[h], off);

    __shared__ float red[4][HEADS];
    if (lane == 0)
#pragma unroll
        for (int h = 0; h < HEADS; ++h) red[warp][h] = acc[h];
    __syncthreads();
    if (threadIdx.x < HEADS) {
        float s = red[0][threadIdx.x] + red[1][threadIdx.x] +
                  red[2][threadIdx.x] + red[3][threadIdx.x];
        g_table[p * HEADS + threadIdx.x] = s;
    }
}

// ---------------------------------------------------------------------------
// Kernel 2: bias[h][i][j] = 16*sigmoid(table[rel_idx[i][j]][h])
// ---------------------------------------------------------------------------
__global__ __launch_bounds__(256) void bias_gather_kernel(const int* __restrict__ rel_idx)
{
    int i = blockIdx.x * 256 + threadIdx.x;
    if (i >= HEADS * SEQ * SEQ) return;
    int h = i >> 12;
    int ij = i & 4095;
    float t = g_table[rel_idx[ij] * HEADS + h];
    g_bias[i] = 16.f / (1.f + expf(-t));
}

// ---------------------------------------------------------------------------
// Kernel 3: qkv GEMM  Y[m][c] = sum_k x[m][k]*W[c][k] + qkvbias[c]
// 128x128 tile, BK=8, 256 threads, 8x8 micro-tile.
// Epilogue scatters into g_Q/g_K/g_V in [b][h][n][d] layout.
// grid = (768/128=6, 131072/128=1024)
// ---------------------------------------------------------------------------
__global__ __launch_bounds__(256) void qkv_gemm(
    const float* __restrict__ x, const float* __restrict__ w,
    const float* __restrict__ q_bias, const float* __restrict__ v_bias)
{
    __shared__ float As[8][128];
    __shared__ float Bs[8][128];
    int tid = threadIdx.x;
    int m0 = blockIdx.y * 128;
    int n0 = blockIdx.x * 128;

    int lr = tid >> 1;            // 0..127
    int lk = (tid & 1) * 4;       // 0 or 4
    const float4* xg = (const float4*)(x + (size_t)(m0 + lr) * KDIM + lk);
    const float4* wg = (const float4*)(w + (size_t)(n0 + lr) * KDIM + lk);

    int ty = tid >> 4, tx = tid & 15;
    float acc[8][8];
#pragma unroll
    for (int i = 0; i < 8; ++i)
#pragma unroll
        for (int j = 0; j < 8; ++j) acc[i][j] = 0.f;

    for (int k0 = 0; k0 < KDIM; k0 += 8) {
        float4 av = *xg; xg += 2;
        float4 bv = *wg; wg += 2;
        As[lk + 0][lr] = av.x; As[lk + 1][lr] = av.y;
        As[lk + 2][lr] = av.z; As[lk + 3][lr] = av.w;
        Bs[lk + 0][lr] = bv.x; Bs[lk + 1][lr] = bv.y;
        Bs[lk + 2][lr] = bv.z; Bs[lk + 3][lr] = bv.w;
        __syncthreads();
#pragma unroll
        for (int kk = 0; kk < 8; ++kk) {
            float a[8], b[8];
            *(float4*)(a)     = *(const float4*)&As[kk][ty * 8];
            *(float4*)(a + 4) = *(const float4*)&As[kk][ty * 8 + 4];
            *(float4*)(b)     = *(const float4*)&Bs[kk][tx * 8];
            *(float4*)(b + 4) = *(const float4*)&Bs[kk][tx * 8 + 4];
#pragma unroll
            for (int i = 0; i < 8; ++i)
#pragma unroll
                for (int j = 0; j < 8; ++j)
                    acc[i][j] = fmaf(a[i], b[j], acc[i][j]);
        }
        __syncthreads();
    }

#pragma unroll
    for (int i = 0; i < 8; ++i) {
        int m = m0 + ty * 8 + i;
        int bw = m >> 6, n = m & 63;
#pragma unroll
        for (int j = 0; j < 8; ++j) {
            int c = n0 + tx * 8 + j;
            float bias = (c < 256) ? q_bias[c] : ((c < 512) ? 0.f : v_bias[c - 512]);
            float val = acc[i][j] + bias;
            int which = c >> 8;
            int h = (c >> 5) & 7;
            int d = c & 31;
            float* dst = (which == 0) ? g_Q : ((which == 1) ? g_K : g_V);
            dst[(size_t)((bw * 8 + h) * 64 + n) * 32 + d] = val;
        }
    }
}

// ---------------------------------------------------------------------------
// Kernel 4: fused attention per window. grid = BWIN, 256 threads.
// ---------------------------------------------------------------------------
__global__ __launch_bounds__(256) void attn_kernel(
    const float* __restrict__ mask, const float* __restrict__ logit_scale)
{
    __shared__ float qs[64][33];
    __shared__ float ks[64][33];
    __shared__ float vs[64][33];
    __shared__ float at[64][65];

    int b = blockIdx.x;
    int tid = threadIdx.x;
    int lane = tid & 31, warp = tid >> 5;
    int w_idx = b & (NW - 1);

    for (int h = 0; h < HEADS; ++h) {
        float sc = expf(fminf(logit_scale[h], 4.6051701859880913f)); // log(100)
        const float* Qg = g_Q + (size_t)(b * 8 + h) * 2048;
        const float* Kg = g_K + (size_t)(b * 8 + h) * 2048;
        const float* Vg = g_V + (size_t)(b * 8 + h) * 2048;
#pragma unroll
        for (int i = tid; i < 2048; i += 256) {
            int r = i >> 5, d = i & 31;
            qs[r][d] = Qg[i];
            ks[r][d] = Kg[i];
            vs[r][d] = Vg[i];
        }
        __syncthreads();

        // L2-normalize q and k rows (row = 32 floats = 1 lane each)
        for (int r = warp; r < 128; r += 8) {
            float* row = (r < 64) ? qs[r] : ks[r - 64];
            float vv = row[lane];
            float ss = vv * vv;
#pragma unroll
            for (int off = 16; off; off >>= 1)
                ss += __shfl_xor_sync(0xffffffffu, ss, off);
            float inv = 1.f / fmaxf(sqrtf(ss), 1e-12f);
            row[lane] = vv * inv;
        }
        __syncthreads();

        // logits: 4x4 register tile per thread
        int ig = tid >> 4;   // 0..15 : rows ig*4..ig*4+3
        int jg = tid & 15;   // cols jg + 16*jj
        float acc[4][4];
#pragma unroll
        for (int ii = 0; ii < 4; ++ii)
#pragma unroll
            for (int jj = 0; jj < 4; ++jj) acc[ii][jj] = 0.f;

#pragma unroll
        for (int d = 0; d < 32; ++d) {
            float a0 = qs[ig * 4 + 0][d];
            float a1 = qs[ig * 4 + 1][d];
            float a2 = qs[ig * 4 + 2][d];
            float a3 = qs[ig * 4 + 3][d];
#pragma unroll
            for (int jj = 0; jj < 4; ++jj) {
                float kv = ks[jg + 16 * jj][d];
                acc[0][jj] = fmaf(a0, kv, acc[0][jj]);
                acc[1][jj] = fmaf(a1, kv, acc[1][jj]);
                acc[2][jj] = fmaf(a2, kv, acc[2][jj]);
                acc[3][jj] = fmaf(a3, kv, acc[3][jj]);
            }
        }
        const float* bia = g_bias + h * 4096;
        const float* msk = mask + (size_t)w_idx * 4096;
#pragma unroll
        for (int ii = 0; ii < 4; ++ii) {
            int i = ig * 4 + ii;
#pragma unroll
            for (int jj = 0; jj < 4; ++jj) {
                int j = jg + 16 * jj;
                at[i][j] = fmaf(sc, acc[ii][jj], bia[i * 64 + j] + msk[i * 64 + j]);
            }
        }
        __syncthreads();

        // softmax per row (2 cols/lane)
        for (int r = warp; r < 64; r += 8) {
            float x0 = at[r][lane], x1 = at[r][lane + 32];
            float mx = fmaxf(x0, x1);
#pragma unroll
            for (int off = 16; off; off >>= 1)
                mx = fmaxf(mx, __shfl_xor_sync(0xffffffffu, mx, off));
            float e0 = expf(x0 - mx), e1 = expf(x1 - mx);
            float s = e0 + e1;
#pragma unroll
            for (int off = 16; off; off >>= 1)
                s += __shfl_xor_sync(0xffffffffu, s, off);
            float inv = 1.f / s;
            at[r][lane] = e0 * inv;
            at[r][lane + 32] = e1 * inv;
        }
        __syncthreads();

        // O = attn @ V : warp handles rows warp*8..+7, lane = d
        float o[8];
#pragma unroll
        for (int ii = 0; ii < 8; ++ii) o[ii] = 0.f;
#pragma unroll 4
        for (int j = 0; j < 64; ++j) {
            float vj = vs[j][lane];
#pragma unroll
            for (int ii = 0; ii < 8; ++ii)
                o[ii] = fmaf(at[warp * 8 + ii][j], vj, o[ii]);
        }
        float* Og = g_O + (size_t)b * 64 * 256 + h * 32;
#pragma unroll
        for (int ii = 0; ii < 8; ++ii)
            Og[(size_t)(warp * 8 + ii) * 256 + lane] = o[ii];
        __syncthreads();
    }
}

// ---------------------------------------------------------------------------
// Kernel 5: proj GEMM  out[m][c] = sum_k O[m][k]*Wp[c][k] + pb[c]
// grid = (256/128=2, 1024)
// ---------------------------------------------------------------------------
__global__ __launch_bounds__(256) void proj_gemm(
    const float* __restrict__ w, const float* __restrict__ pb,
    float* __restrict__ out)
{
    __shared__ float As[8][128];
    __shared__ float Bs[8][128];
    int tid = threadIdx.x;
    int m0 = blockIdx.y * 128;
    int n0 = blockIdx.x * 128;

    int lr = tid >> 1;
    int lk = (tid & 1) * 4;
    const float4* xg = (const float4*)(g_O + (size_t)(m0 + lr) * KDIM + lk);
    const float4* wg = (const float4*)(w + (size_t)(n0 + lr) * KDIM + lk);

    int ty = tid >> 4, tx = tid & 15;
    float acc[8][8];
#pragma unroll
    for (int i = 0; i < 8; ++i)
#pragma unroll
        for (int j = 0; j < 8; ++j) acc[i][j] = 0.f;

    for (int k0 = 0; k0 < KDIM; k0 += 8) {
        float4 av = *xg; xg += 2;
        float4 bv = *wg; wg += 2;
        As[lk + 0][lr] = av.x; As[lk + 1][lr] = av.y;
        As[lk + 2][lr] = av.z; As[lk + 3][lr] = av.w;
        Bs[lk + 0][lr] = bv.x; Bs[lk + 1][lr] = bv.y;
        Bs[lk + 2][lr] = bv.z; Bs[lk + 3][lr] = bv.w;
        __syncthreads();
#pragma unroll
        for (int kk = 0; kk < 8; ++kk) {
            float a[8], bfr[8];
            *(float4*)(a)       = *(const float4*)&As[kk][ty * 8];
            *(float4*)(a + 4)   = *(const float4*)&As[kk][ty * 8 + 4];
            *(float4*)(bfr)     = *(const float4*)&Bs[kk][tx * 8];
            *(float4*)(bfr + 4) = *(const float4*)&Bs[kk][tx * 8 + 4];
#pragma unroll
            for (int i = 0; i < 8; ++i)
#pragma unroll
                for (int j = 0; j < 8; ++j)
                    acc[i][j] = fmaf(a[i], bfr[j], acc[i][j]);
        }
        __syncthreads();
    }

#pragma unroll
    for (int i = 0; i < 8; ++i) {
        int m = m0 + ty * 8 + i;
#pragma unroll
        for (int j = 0; j < 8; ++j) {
            int c = n0 + tx * 8 + j;
            out[(size_t)m * 256 + c] = acc[i][j] + pb[c];
        }
    }
}

// ---------------------------------------------------------------------------
extern "C" void kernel_launch(void* const* d_in, const int* in_sizes, int n_in,
                              void* d_out, int out_size)
{
    const float* x           = (const float*)d_in[0];
    const float* mask        = (const float*)d_in[1];
    const float* qkv_w       = (const float*)d_in[2];
    const float* q_bias      = (const float*)d_in[3];
    const float* v_bias      = (const float*)d_in[4];
    const float* logit_scale = (const float*)d_in[5];
    const float* cpb_w1      = (const float*)d_in[6];
    const float* cpb_b1      = (const float*)d_in[7];
    const float* cpb_w2      = (const float*)d_in[8];
    const float* proj_w      = (const float*)d_in[9];
    const float* proj_b      = (const float*)d_in[10];
    const float* coords      = (const float*)d_in[11];
    const int*   rel_idx     = (const int*)d_in[12];
    float* out = (float*)d_out;

    cpb_table_kernel<<<TBL, 128>>>(cpb_w1, cpb_b1, cpb_w2, coords);
    bias_gather_kernel<<<(HEADS * SEQ * SEQ + 255) / 256, 256>>>(rel_idx);
    qkv_gemm<<<dim3(6, 1024), 256>>>(x, qkv_w, q_bias, v_bias);
    attn_kernel<<<BWIN, 256>>>(mask, logit_scale);
    proj_gemm<<<dim3(2, 1024), 256>>>(proj_w, proj_b, out);
}

// round 3
// speedup vs baseline: 1.5064x; 1.5064x over previous
#include <cuda_runtime.h>
#include <cstdint>
#include <math.h>

// Problem constants
#define BWIN   2048
#define SEQ    64
#define DIM    256
#define HEADS  8
#define HD     32
#define NW     64
#define KDIM   256
#define TBL    225
#define CPBH   512

// Scratch (device globals)
__device__ float g_Q[BWIN * HEADS * SEQ * HD];
__device__ float g_K[BWIN * HEADS * SEQ * HD];
__device__ float g_V[BWIN * HEADS * SEQ * HD];
__device__ float g_O[BWIN * SEQ * DIM];
__device__ float g_table[TBL * HEADS];
__device__ float g_bias[HEADS * SEQ * SEQ];

// SW128 swizzle on byte offsets (128B rows)
#define SWZ(b) ((b) ^ (((b) >> 3) & 0x70))

__device__ __forceinline__ uint32_t tf32_rna(float x) {
    uint32_t r;
    asm("cvt.rna.tf32.f32 %0, %1;" : "=r"(r) : "f"(x));
    return r;
}

__device__ __forceinline__ void split4(float4 v, uint4& hi, uint4& lo) {
    hi.x = tf32_rna(v.x); lo.x = tf32_rna(v.x - __uint_as_float(hi.x));
    hi.y = tf32_rna(v.y); lo.y = tf32_rna(v.y - __uint_as_float(hi.y));
    hi.z = tf32_rna(v.z); lo.z = tf32_rna(v.z - __uint_as_float(hi.z));
    hi.w = tf32_rna(v.w); lo.w = tf32_rna(v.w - __uint_as_float(hi.w));
}

__device__ __forceinline__ void mma1688(float* c,
    uint32_t a0, uint32_t a1, uint32_t a2, uint32_t a3,
    uint32_t b0, uint32_t b1)
{
    asm volatile(
        "mma.sync.aligned.m16n8k8.row.col.f32.tf32.tf32.f32 "
        "{%0,%1,%2,%3},{%4,%5,%6,%7},{%8,%9},{%0,%1,%2,%3};"
        : "+f"(c[0]), "+f"(c[1]), "+f"(c[2]), "+f"(c[3])
        : "r"(a0), "r"(a1), "r"(a2), "r"(a3), "r"(b0), "r"(b1));
}

// ---------------------------------------------------------------------------
// Kernel 1: CPB MLP
// ---------------------------------------------------------------------------
__global__ __launch_bounds__(128) void cpb_table_kernel(
    const float* __restrict__ w1, const float* __restrict__ b1,
    const float* __restrict__ w2, const float* __restrict__ coords)
{
    int p = blockIdx.x;
    float c0 = coords[2 * p + 0];
    float c1 = coords[2 * p + 1];
    float acc[HEADS];
#pragma unroll
    for (int h = 0; h < HEADS; ++h) acc[h] = 0.f;

    for (int j = threadIdx.x; j < CPBH; j += 128) {
        float hid = fmaf(w1[2 * j], c0, fmaf(w1[2 * j + 1], c1, b1[j]));
        hid = fmaxf(hid, 0.f);
#pragma unroll
        for (int h = 0; h < HEADS; ++h)
            acc[h] = fmaf(hid, w2[h * CPBH + j], acc[h]);
    }
    int lane = threadIdx.x & 31, warp = threadIdx.x >> 5;
#pragma unroll
    for (int h = 0; h < HEADS; ++h)
#pragma unroll
        for (int off = 16; off; off >>= 1)
            acc[h] += __shfl_xor_sync(0xffffffffu, acc[h], off);

    __shared__ float red[4][HEADS];
    if (lane == 0)
#pragma unroll
        for (int h = 0; h < HEADS; ++h) red[warp][h] = acc[h];
    __syncthreads();
    if (threadIdx.x < HEADS) {
        float s = red[0][threadIdx.x] + red[1][threadIdx.x] +
                  red[2][threadIdx.x] + red[3][threadIdx.x];
        g_table[p * HEADS + threadIdx.x] = s;
    }
}

// ---------------------------------------------------------------------------
// Kernel 2: bias gather + 16*sigmoid
// ---------------------------------------------------------------------------
__global__ __launch_bounds__(256) void bias_gather_kernel(const int* __restrict__ rel_idx)
{
    int i = blockIdx.x * 256 + threadIdx.x;
    if (i >= HEADS * SEQ * SEQ) return;
    int h = i >> 12;
    int ij = i & 4095;
    float t = g_table[rel_idx[ij] * HEADS + h];
    g_bias[i] = 16.f / (1.f + expf(-t));
}

// ---------------------------------------------------------------------------
// 3xTF32 mma.sync GEMM: D[m][c] = sum_k A[m][k]*B[c][k]
// CTA: 128x128 tile, 128 threads (4 warps, each 64x64), BK=32, K=256.
// smem regions (bytes): Ahi 0, Alo 16384, Bhi 32768, Blo 49152. Total 64KB.
// mode 0: A = x,   epilogue scatters to g_Q/g_K/g_V with qkv bias
// mode 1: A = g_O, epilogue writes out + proj bias
// ---------------------------------------------------------------------------
#define GSMEM_TOTAL 65536

__global__ __launch_bounds__(128, 2) void mma_gemm(
    const float* __restrict__ A_in, const float* __restrict__ B,
    const float* __restrict__ q_bias, const float* __restrict__ v_bias,
    const float* __restrict__ pb, float* __restrict__ out, int mode)
{
    extern __shared__ char sm[];
    const float* A = (mode == 0) ? A_in : g_O;
    int tid = threadIdx.x;
    int lane = tid & 31, warp = tid >> 5;
    int m0 = blockIdx.y * 128;
    int n0 = blockIdx.x * 128;
    int wm = (warp >> 1) * 64;   // warp row offset in tile
    int wn = (warp & 1) * 64;    // warp col offset in tile

    float acc[4][8][4];
#pragma unroll
    for (int mi = 0; mi < 4; ++mi)
#pragma unroll
        for (int ni = 0; ni < 8; ++ni)
#pragma unroll
            for (int q = 0; q < 4; ++q) acc[mi][ni][q] = 0.f;

    int lrow = tid >> 3;     // 0..15
    int lc4 = tid & 7;       // 0..7 (float4 index within 32-wide k chunk)

    // precompute fragment smem byte offsets (row part varies in loops)
    int g = lane >> 2;       // 0..7 row group
    int tk = lane & 3;       // 0..3 k-in-group

    for (int ko = 0; ko < KDIM; ko += 32) {
        __syncthreads();
        // stage load: A rows m0..m0+127, B rows n0..n0+127, k = ko..ko+31
#pragma unroll
        for (int q = 0; q < 8; ++q) {
            int r = lrow + q * 16;
            uint32_t base = (uint32_t)(r * 128 + lc4 * 16);
            uint32_t so = SWZ(base);
            float4 av = *(const float4*)(A + (size_t)(m0 + r) * KDIM + ko + lc4 * 4);
            uint4 ah, al;
            split4(av, ah, al);
            *(uint4*)(sm + so) = ah;
            *(uint4*)(sm + 16384 + so) = al;
            float4 bv = *(const float4*)(B + (size_t)(n0 + r) * KDIM + ko + lc4 * 4);
            uint4 bh, bl;
            split4(bv, bh, bl);
            *(uint4*)(sm + 32768 + so) = bh;
            *(uint4*)(sm + 49152 + so) = bl;
        }
        __syncthreads();

#pragma unroll
        for (int kk = 0; kk < 32; kk += 8) {
            uint32_t Ah[4][4], Al[4][4];
#pragma unroll
            for (int mi = 0; mi < 4; ++mi) {
                int r0 = wm + mi * 16 + g;
                int ck = kk + tk;
                uint32_t o00 = SWZ((uint32_t)(r0 * 128 + ck * 4));
                uint32_t o10 = SWZ((uint32_t)((r0 + 8) * 128 + ck * 4));
                uint32_t o01 = SWZ((uint32_t)(r0 * 128 + (ck + 4) * 4));
                uint32_t o11 = SWZ((uint32_t)((r0 + 8) * 128 + (ck + 4) * 4));
                Ah[mi][0] = *(const uint32_t*)(sm + o00);
                Ah[mi][1] = *(const uint32_t*)(sm + o10);
                Ah[mi][2] = *(const uint32_t*)(sm + o01);
                Ah[mi][3] = *(const uint32_t*)(sm + o11);
                Al[mi][0] = *(const uint32_t*)(sm + 16384 + o00);
                Al[mi][1] = *(const uint32_t*)(sm + 16384 + o10);
                Al[mi][2] = *(const uint32_t*)(sm + 16384 + o01);
                Al[mi][3] = *(const uint32_t*)(sm + 16384 + o11);
            }
#pragma unroll
            for (int ni = 0; ni < 8; ++ni) {
                int nr = wn + ni * 8 + g;
                int ck = kk + tk;
                uint32_t ob0 = SWZ((uint32_t)(nr * 128 + ck * 4));
                uint32_t ob1 = SWZ((uint32_t)(nr * 128 + (ck + 4) * 4));
                uint32_t bh0 = *(const uint32_t*)(sm + 32768 + ob0);
                uint32_t bh1 = *(const uint32_t*)(sm + 32768 + ob1);
                uint32_t bl0 = *(const uint32_t*)(sm + 49152 + ob0);
                uint32_t bl1 = *(const uint32_t*)(sm + 49152 + ob1);
#pragma unroll
                for (int mi = 0; mi < 4; ++mi) {
                    mma1688(acc[mi][ni], Ah[mi][0], Ah[mi][1], Ah[mi][2], Ah[mi][3], bh0, bh1);
                    mma1688(acc[mi][ni], Al[mi][0], Al[mi][1], Al[mi][2], Al[mi][3], bh0, bh1);
                    mma1688(acc[mi][ni], Ah[mi][0], Ah[mi][1], Ah[mi][2], Ah[mi][3], bl0, bl1);
                }
            }
        }
    }

    // Epilogue
#pragma unroll
    for (int mi = 0; mi < 4; ++mi) {
#pragma unroll
        for (int ni = 0; ni < 8; ++ni) {
            int r = m0 + wm + mi * 16 + g;        // rows r and r+8
            int c = n0 + wn + ni * 8 + 2 * tk;    // cols c, c+1
            if (mode == 0) {
                int which = c >> 8;
                int h = (c >> 5) & 7;
                int d = c & 31;
                float b0, b1;
                if (which == 0)      { b0 = q_bias[c];       b1 = q_bias[c + 1]; }
                else if (which == 2) { b0 = v_bias[c - 512]; b1 = v_bias[c - 511]; }
                else                 { b0 = 0.f; b1 = 0.f; }
                float* baseP = (which == 0) ? g_Q : (which == 1) ? g_K : g_V;
                int bw0 = r >> 6, n_0 = r & 63;
                int bw1 = (r + 8) >> 6, n_1 = (r + 8) & 63;
                float2 v0 = make_float2(acc[mi][ni][0] + b0, acc[mi][ni][1] + b1);
                float2 v1 = make_float2(acc[mi][ni][2] + b0, acc[mi][ni][3] + b1);
                *(float2*)(baseP + (size_t)((bw0 * 8 + h) * 64 + n_0) * 32 + d) = v0;
                *(float2*)(baseP + (size_t)((bw1 * 8 + h) * 64 + n_1) * 32 + d) = v1;
            } else {
                float b0 = pb[c], b1 = pb[c + 1];
                float2 v0 = make_float2(acc[mi][ni][0] + b0, acc[mi][ni][1] + b1);
                float2 v1 = make_float2(acc[mi][ni][2] + b0, acc[mi][ni][3] + b1);
                *(float2*)(out + (size_t)r * 256 + c) = v0;
                *(float2*)(out + (size_t)(r + 8) * 256 + c) = v1;
            }
        }
    }
}

// ---------------------------------------------------------------------------
// Kernel 4: fused attention per window (unchanged)
// ---------------------------------------------------------------------------
__global__ __launch_bounds__(256) void attn_kernel(
    const float* __restrict__ mask, const float* __restrict__ logit_scale)
{
    __shared__ float qs[64][33];
    __shared__ float ks[64][33];
    __shared__ float vs[64][33];
    __shared__ float at[64][65];

    int b = blockIdx.x;
    int tid = threadIdx.x;
    int lane = tid & 31, warp = tid >> 5;
    int w_idx = b & (NW - 1);

    for (int h = 0; h < HEADS; ++h) {
        float sc = expf(fminf(logit_scale[h], 4.6051701859880913f)); // log(100)
        const float* Qg = g_Q + (size_t)(b * 8 + h) * 2048;
        const float* Kg = g_K + (size_t)(b * 8 + h) * 2048;
        const float* Vg = g_V + (size_t)(b * 8 + h) * 2048;
#pragma unroll
        for (int i = tid; i < 2048; i += 256) {
            int r = i >> 5, d = i & 31;
            qs[r][d] = Qg[i];
            ks[r][d] = Kg[i];
            vs[r][d] = Vg[i];
        }
        __syncthreads();

        for (int r = warp; r < 128; r += 8) {
            float* row = (r < 64) ? qs[r] : ks[r - 64];
            float vv = row[lane];
            float ss = vv * vv;
#pragma unroll
            for (int off = 16; off; off >>= 1)
                ss += __shfl_xor_sync(0xffffffffu, ss, off);
            float inv = 1.f / fmaxf(sqrtf(ss), 1e-12f);
            row[lane] = vv * inv;
        }
        __syncthreads();

        int ig = tid >> 4;
        int jg = tid & 15;
        float acc[4][4];
#pragma unroll
        for (int ii = 0; ii < 4; ++ii)
#pragma unroll
            for (int jj = 0; jj < 4; ++jj) acc[ii][jj] = 0.f;

#pragma unroll
        for (int d = 0; d < 32; ++d) {
            float a0 = qs[ig * 4 + 0][d];
            float a1 = qs[ig * 4 + 1][d];
            float a2 = qs[ig * 4 + 2][d];
            float a3 = qs[ig * 4 + 3][d];
#pragma unroll
            for (int jj = 0; jj < 4; ++jj) {
                float kv = ks[jg + 16 * jj][d];
                acc[0][jj] = fmaf(a0, kv, acc[0][jj]);
                acc[1][jj] = fmaf(a1, kv, acc[1][jj]);
                acc[2][jj] = fmaf(a2, kv, acc[2][jj]);
                acc[3][jj] = fmaf(a3, kv, acc[3][jj]);
            }
        }
        const float* bia = g_bias + h * 4096;
        const float* msk = mask + (size_t)w_idx * 4096;
#pragma unroll
        for (int ii = 0; ii < 4; ++ii) {
            int i = ig * 4 + ii;
#pragma unroll
            for (int jj = 0; jj < 4; ++jj) {
                int j = jg + 16 * jj;
                at[i][j] = fmaf(sc, acc[ii][jj], bia[i * 64 + j] + msk[i * 64 + j]);
            }
        }
        __syncthreads();

        for (int r = warp; r < 64; r += 8) {
            float x0 = at[r][lane], x1 = at[r][lane + 32];
            float mx = fmaxf(x0, x1);
#pragma unroll
            for (int off = 16; off; off >>= 1)
                mx = fmaxf(mx, __shfl_xor_sync(0xffffffffu, mx, off));
            float e0 = expf(x0 - mx), e1 = expf(x1 - mx);
            float s = e0 + e1;
#pragma unroll
            for (int off = 16; off; off >>= 1)
                s += __shfl_xor_sync(0xffffffffu, s, off);
            float inv = 1.f / s;
            at[r][lane] = e0 * inv;
            at[r][lane + 32] = e1 * inv;
        }
        __syncthreads();

        float o[8];
#pragma unroll
        for (int ii = 0; ii < 8; ++ii) o[ii] = 0.f;
#pragma unroll 4
        for (int j = 0; j < 64; ++j) {
            float vj = vs[j][lane];
#pragma unroll
            for (int ii = 0; ii < 8; ++ii)
                o[ii] = fmaf(at[warp * 8 + ii][j], vj, o[ii]);
        }
        float* Og = g_O + (size_t)b * 64 * 256 + h * 32;
#pragma unroll
        for (int ii = 0; ii < 8; ++ii)
            Og[(size_t)(warp * 8 + ii) * 256 + lane] = o[ii];
        __syncthreads();
    }
}

// ---------------------------------------------------------------------------
extern "C" void kernel_launch(void* const* d_in, const int* in_sizes, int n_in,
                              void* d_out, int out_size)
{
    const float* x           = (const float*)d_in[0];
    const float* mask        = (const float*)d_in[1];
    const float* qkv_w       = (const float*)d_in[2];
    const float* q_bias      = (const float*)d_in[3];
    const float* v_bias      = (const float*)d_in[4];
    const float* logit_scale = (const float*)d_in[5];
    const float* cpb_w1      = (const float*)d_in[6];
    const float* cpb_b1      = (const float*)d_in[7];
    const float* cpb_w2      = (const float*)d_in[8];
    const float* proj_w      = (const float*)d_in[9];
    const float* proj_b      = (const float*)d_in[10];
    const float* coords      = (const float*)d_in[11];
    const int*   rel_idx     = (const int*)d_in[12];
    float* out = (float*)d_out;

    static int configured = 0;
    if (!configured) {
        cudaFuncSetAttribute(mma_gemm, cudaFuncAttributeMaxDynamicSharedMemorySize,
                             GSMEM_TOTAL);
        configured = 1;
    }

    cpb_table_kernel<<<TBL, 128>>>(cpb_w1, cpb_b1, cpb_w2, coords);
    bias_gather_kernel<<<(HEADS * SEQ * SEQ + 255) / 256, 256>>>(rel_idx);
    mma_gemm<<<dim3(6, 1024), 128, GSMEM_TOTAL>>>(x, qkv_w, q_bias, v_bias,
                                                  nullptr, nullptr, 0);
    attn_kernel<<<BWIN, 256>>>(mask, logit_scale);
    mma_gemm<<<dim3(2, 1024), 128, GSMEM_TOTAL>>>(nullptr, proj_w, nullptr, nullptr,
                                                  proj_b, out, 1);
}